// round 7
// baseline (speedup 1.0000x reference)
#include <cuda_runtime.h>
#include <cstdint>
#include <cstddef>
#include <math.h>

#define DI __device__ __forceinline__

static constexpr int NR = 8192;
static constexpr int HD = 256;
static constexpr int BM = 128;
static constexpr int BN = 128;
static constexpr int BK = 64;
static constexpr int STAGES = 3;
static constexpr int NTHREADS = 512;    // 16 warps: 4(M) x 4(N), warp tile 32x32

static constexpr int A_ROW_F = 68;      // 64 data + 4 pad floats
static constexpr int B_ROW_F = 136;     // 128 data + 8 pad floats
static constexpr int STAGE_F = 8704;    // floats per stage (A: 128x68, B: 64x136 — equal)
static constexpr int SMEM_DEG_B = 512;
static constexpr int SMEM_TOTAL = SMEM_DEG_B + 2 * STAGES * STAGE_F * 4;  // 209408

__device__ float g_P[(size_t)NR * HD];  // inputs @ W, stored as tf32-rounded bit patterns

DI uint32_t smem_u32(const void* p) {
    uint32_t a;
    asm("{ .reg .u64 t; cvta.to.shared.u64 t, %1; cvt.u32.u64 %0, t; }" : "=r"(a) : "l"(p));
    return a;
}
DI void cp_async16(uint32_t dst, const void* src) {
    asm volatile("cp.async.cg.shared.global [%0], [%1], 16;" :: "r"(dst), "l"(src) : "memory");
}
DI void cp_commit() { asm volatile("cp.async.commit_group;" ::: "memory"); }
template <int N> DI void cp_wait() { asm volatile("cp.async.wait_group %0;" :: "n"(N) : "memory"); }
DI uint32_t f2tf32(float f) {
    uint32_t u;
    asm("cvt.rna.tf32.f32 %0, %1;" : "=r"(u) : "f"(f));
    return u;
}
DI void mma_tf32(float* d, const uint32_t* a, const uint32_t* b) {
    asm volatile(
        "mma.sync.aligned.m16n8k8.row.col.f32.tf32.tf32.f32 "
        "{%0,%1,%2,%3}, {%4,%5,%6,%7}, {%8,%9}, {%0,%1,%2,%3};"
        : "+f"(d[0]), "+f"(d[1]), "+f"(d[2]), "+f"(d[3])
        : "r"(a[0]), "r"(a[1]), "r"(a[2]), "r"(a[3]), "r"(b[0]), "r"(b[1]));
}

DI void load_chunk(float* sA, float* sB, int s,
                   const float* __restrict__ A, int lda, int R0,
                   const float* __restrict__ B, int ldb, int N0,
                   int k0, int tid) {
    uint32_t aAddr = smem_u32(sA + s * STAGE_F);
    uint32_t bAddr = smem_u32(sB + s * STAGE_F);
#pragma unroll
    for (int i = 0; i < 4; ++i) {                      // A: 2048 x 16B
        int idx = tid + i * NTHREADS;
        int r = idx >> 4, c = idx & 15;
        cp_async16(aAddr + (uint32_t)(r * (A_ROW_F * 4) + c * 16),
                   A + (size_t)(R0 + r) * lda + k0 + c * 4);
    }
#pragma unroll
    for (int i = 0; i < 4; ++i) {                      // B: 2048 x 16B
        int idx = tid + i * NTHREADS;
        int r = idx >> 5, c = idx & 31;
        cp_async16(bAddr + (uint32_t)(r * (B_ROW_F * 4) + c * 16),
                   B + (size_t)(k0 + r) * ldb + N0 + c * 4);
    }
}

// Fragment loads for one ks step. MODE 0 -> cvt.rna; MODE 1 -> raw fp32 bits (HW trunc).
template <int MODE>
DI void load_frags(const float* __restrict__ aS, const float* __restrict__ bS,
                   int aBase, int bBase, int ks,
                   uint32_t af[2][4], uint32_t bf[4][2],
                   float dsum[2][2], bool doDeg) {
#pragma unroll
    for (int mt = 0; mt < 2; ++mt) {
        int base = aBase + mt * 16 * A_ROW_F + ks * 8;
        float f0 = aS[base];
        float f1 = aS[base + 8 * A_ROW_F];
        float f2 = aS[base + 4];
        float f3 = aS[base + 8 * A_ROW_F + 4];
        if (MODE == 1 && doDeg) {
            dsum[mt][0] += f0 + f2;
            dsum[mt][1] += f1 + f3;
        }
        if (MODE == 0) {
            af[mt][0] = f2tf32(f0); af[mt][1] = f2tf32(f1);
            af[mt][2] = f2tf32(f2); af[mt][3] = f2tf32(f3);
        } else {
            af[mt][0] = __float_as_uint(f0); af[mt][1] = __float_as_uint(f1);
            af[mt][2] = __float_as_uint(f2); af[mt][3] = __float_as_uint(f3);
        }
    }
#pragma unroll
    for (int nt = 0; nt < 4; ++nt) {
        int base = bBase + ks * 8 * B_ROW_F + nt * 8;
        float b0 = bS[base];
        float b1 = bS[base + 4 * B_ROW_F];
        if (MODE == 0) {
            bf[nt][0] = f2tf32(b0); bf[nt][1] = f2tf32(b1);
        } else {
            bf[nt][0] = __float_as_uint(b0); bf[nt][1] = __float_as_uint(b1);
        }
    }
}

// MODE 0: g_P = tf32_round(inputs @ W)
// MODE 1: out = tanh((adj @ P + P_selfrow) / (rowsum(adj)+1) + b)
template <int MODE>
__global__ void __launch_bounds__(NTHREADS, 1)
gemm_gcn(const float* __restrict__ A, const float* __restrict__ Bext,
         float* __restrict__ out, const float* __restrict__ bias) {
    extern __shared__ char smem[];
    float* sdeg = (float*)smem;
    float* sA = (float*)(smem + SMEM_DEG_B);
    float* sB = sA + STAGES * STAGE_F;

    const int tid = threadIdx.x;
    const int lane = tid & 31;
    const int wid = tid >> 5;
    const int wm = wid >> 2;            // 0..3 (32 rows each)
    const int wn = wid & 3;             // 0..3 (32 cols each)
    const int q = lane >> 2;            // 0..7
    const int c4 = lane & 3;            // 0..3

    const int Mt = blockIdx.x >> 1;
    const int Nt = blockIdx.x & 1;
    const int R0 = Mt * BM;
    const int N0 = Nt * BN;

    const int lda = (MODE == 0) ? HD : NR;
    const float* Bp = (MODE == 0) ? Bext : g_P;
    const int ldb = HD;
    const int NCH = ((MODE == 0) ? HD : NR) / BK;
    const bool doDeg = (MODE == 1) && (wn == 0);

    float acc[2][4][4];
#pragma unroll
    for (int i = 0; i < 2; ++i)
#pragma unroll
        for (int j = 0; j < 4; ++j)
#pragma unroll
            for (int e = 0; e < 4; ++e) acc[i][j][e] = 0.0f;
    float dsum[2][2];
    dsum[0][0] = dsum[0][1] = dsum[1][0] = dsum[1][1] = 0.0f;

    // prologue: stages 0,1
    load_chunk(sA, sB, 0, A, lda, R0, Bp, ldb, N0, 0, tid);
    cp_commit();
    load_chunk(sA, sB, 1, A, lda, R0, Bp, ldb, N0, BK, tid);
    cp_commit();

    const int aBase = (wm * 32 + q) * A_ROW_F + c4;
    const int bBase = c4 * B_ROW_F + wn * 32 + q;

    for (int kc = 0; kc < NCH; ++kc) {
        if (kc + 2 < NCH) cp_wait<1>(); else cp_wait<0>();
        __syncthreads();                                    // stage kc ready; kc-1 reads done
        if (kc + 2 < NCH) {
            load_chunk(sA, sB, (kc + 2) % STAGES, A, lda, R0, Bp, ldb, N0, (kc + 2) * BK, tid);
            cp_commit();
        }

        const float* aS = sA + (kc % STAGES) * STAGE_F;
        const float* bS = sB + (kc % STAGES) * STAGE_F;

        uint32_t af[2][2][4], bf[2][4][2];
        load_frags<MODE>(aS, bS, aBase, bBase, 0, af[0], bf[0], dsum, doDeg);
#pragma unroll
        for (int ks = 0; ks < BK / 8; ++ks) {               // 8 steps: FULL BK=64
            const int c = ks & 1;
            if (ks < BK / 8 - 1)
                load_frags<MODE>(aS, bS, aBase, bBase, ks + 1, af[c ^ 1], bf[c ^ 1], dsum, doDeg);
#pragma unroll
            for (int mt = 0; mt < 2; ++mt)
#pragma unroll
                for (int nt = 0; nt < 4; ++nt)
                    mma_tf32(acc[mt][nt], af[c][mt], bf[c][nt]);
        }
    }
    __syncthreads();

    if (MODE == 0) {
#pragma unroll
        for (int mt = 0; mt < 2; ++mt) {
            int rlo = R0 + wm * 32 + mt * 16 + q;
#pragma unroll
            for (int nt = 0; nt < 4; ++nt) {
                int col = N0 + wn * 32 + nt * 8 + 2 * c4;
                float2 vlo, vhi;
                vlo.x = __uint_as_float(f2tf32(acc[mt][nt][0]));
                vlo.y = __uint_as_float(f2tf32(acc[mt][nt][1]));
                vhi.x = __uint_as_float(f2tf32(acc[mt][nt][2]));
                vhi.y = __uint_as_float(f2tf32(acc[mt][nt][3]));
                *(float2*)&g_P[(size_t)rlo * HD + col] = vlo;
                *(float2*)&g_P[(size_t)(rlo + 8) * HD + col] = vhi;
            }
        }
    } else {
        if (doDeg) {
#pragma unroll
            for (int mt = 0; mt < 2; ++mt) {
#pragma unroll
                for (int h = 0; h < 2; ++h) {
                    float v = dsum[mt][h];
                    v += __shfl_xor_sync(0xffffffffu, v, 1);
                    v += __shfl_xor_sync(0xffffffffu, v, 2);
                    dsum[mt][h] = v;
                }
                if (c4 == 0) {
                    sdeg[wm * 32 + mt * 16 + q] = dsum[mt][0];
                    sdeg[wm * 32 + mt * 16 + q + 8] = dsum[mt][1];
                }
            }
        }
        __syncthreads();
#pragma unroll
        for (int mt = 0; mt < 2; ++mt) {
            int lrow = wm * 32 + mt * 16 + q;
            int rlo = R0 + lrow;
            int rhi = rlo + 8;
            float invlo = 1.0f / (sdeg[lrow] + 1.0f);
            float invhi = 1.0f / (sdeg[lrow + 8] + 1.0f);
#pragma unroll
            for (int nt = 0; nt < 4; ++nt) {
                int col = N0 + wn * 32 + nt * 8 + 2 * c4;
                float2 plo = *(const float2*)&g_P[(size_t)rlo * HD + col];
                float2 phi = *(const float2*)&g_P[(size_t)rhi * HD + col];
                float2 bb = *(const float2*)&bias[col];
                float2 olo, ohi;
                olo.x = tanhf((acc[mt][nt][0] + plo.x) * invlo + bb.x);
                olo.y = tanhf((acc[mt][nt][1] + plo.y) * invlo + bb.y);
                ohi.x = tanhf((acc[mt][nt][2] + phi.x) * invhi + bb.x);
                ohi.y = tanhf((acc[mt][nt][3] + phi.y) * invhi + bb.y);
                *(float2*)&out[(size_t)rlo * HD + col] = olo;
                *(float2*)&out[(size_t)rhi * HD + col] = ohi;
            }
        }
    }
}

extern "C" void kernel_launch(void* const* d_in, const int* in_sizes, int n_in,
                              void* d_out, int out_size) {
    const float* inputs = (const float*)d_in[0];
    const float* adj    = (const float*)d_in[1];
    const float* W      = (const float*)d_in[2];
    const float* b      = (const float*)d_in[3];
    float* out = (float*)d_out;

    cudaFuncSetAttribute(gemm_gcn<0>, cudaFuncAttributeMaxDynamicSharedMemorySize, SMEM_TOTAL);
    cudaFuncSetAttribute(gemm_gcn<1>, cudaFuncAttributeMaxDynamicSharedMemorySize, SMEM_TOTAL);

    gemm_gcn<0><<<(NR / BM) * (HD / BN), NTHREADS, SMEM_TOTAL>>>(inputs, W, nullptr, nullptr);
    gemm_gcn<1><<<(NR / BM) * (HD / BN), NTHREADS, SMEM_TOTAL>>>(adj, nullptr, out, b);
}

// round 10
// speedup vs baseline: 1.4430x; 1.4430x over previous
#include <cuda_runtime.h>
#include <cuda_fp16.h>
#include <cstdint>
#include <cstddef>
#include <math.h>

#define DI __device__ __forceinline__

static constexpr int NR = 8192;
static constexpr int HD = 256;
static constexpr int BM = 128;
static constexpr int BN = 128;
static constexpr int BK = 64;
static constexpr int STAGES = 3;
static constexpr int NTHREADS = 512;    // 16 warps: 4(M) x 4(N), warp tile 32x32

static constexpr int A_ROW_F = 72;      // fp32 floats per A SMEM row (64 data + 8 pad)
static constexpr int B_ROW_H = 72;      // fp16 halves per B SMEM row (64 data + 8 pad)
static constexpr int A_STAGE_B = 128 * A_ROW_F * 4;   // 36864
static constexpr int B_STAGE_B = 128 * B_ROW_H * 2;   // 18432
static constexpr int SMEM_DEG_B = 512;
static constexpr int SMEM_A_OFF = SMEM_DEG_B;
static constexpr int SMEM_B_OFF = SMEM_A_OFF + STAGES * A_STAGE_B;
static constexpr int SMEM_TOTAL = SMEM_B_OFF + STAGES * B_STAGE_B;  // 166400

__device__ __half g_Wt[HD * HD];              // W transposed: [n][k] fp16
__device__ __half g_Ph[(size_t)HD * NR];      // P transposed: [n][k] fp16  (P = inputs @ W)

DI uint32_t smem_u32(const void* p) {
    uint32_t a;
    asm("{ .reg .u64 t; cvta.to.shared.u64 t, %1; cvt.u32.u64 %0, t; }" : "=r"(a) : "l"(p));
    return a;
}
DI void cp_async16(uint32_t dst, const void* src) {
    asm volatile("cp.async.cg.shared.global [%0], [%1], 16;" :: "r"(dst), "l"(src) : "memory");
}
DI void cp_commit() { asm volatile("cp.async.commit_group;" ::: "memory"); }
template <int N> DI void cp_wait() { asm volatile("cp.async.wait_group %0;" :: "n"(N) : "memory"); }
DI uint32_t pack_h2(float lo, float hi) {     // result .lo=lo, .hi=hi
    uint32_t d;
    asm("cvt.rn.f16x2.f32 %0, %1, %2;" : "=r"(d) : "f"(hi), "f"(lo));
    return d;
}
DI void mma_f16(float* d, const uint32_t* a, const uint32_t* b) {
    asm volatile(
        "mma.sync.aligned.m16n8k16.row.col.f32.f16.f16.f32 "
        "{%0,%1,%2,%3}, {%4,%5,%6,%7}, {%8,%9}, {%0,%1,%2,%3};"
        : "+f"(d[0]), "+f"(d[1]), "+f"(d[2]), "+f"(d[3])
        : "r"(a[0]), "r"(a[1]), "r"(a[2]), "r"(a[3]), "r"(b[0]), "r"(b[1]));
}

// A tile [BM][BK] fp32 from row-major A; B tile [BN n-rows][BK k] fp16 from n-major Bh
DI void load_chunk(char* smem, int s,
                   const float* __restrict__ A, int lda, int R0,
                   const __half* __restrict__ Bh, int ldb, int N0,
                   int k0, int tid) {
    uint32_t aAddr = smem_u32(smem + SMEM_A_OFF + s * A_STAGE_B);
    uint32_t bAddr = smem_u32(smem + SMEM_B_OFF + s * B_STAGE_B);
#pragma unroll
    for (int i = 0; i < 4; ++i) {                      // A: 2048 x 16B
        int idx = tid + i * NTHREADS;
        int r = idx >> 4, c = idx & 15;
        cp_async16(aAddr + (uint32_t)(r * (A_ROW_F * 4) + c * 16),
                   A + (size_t)(R0 + r) * lda + k0 + c * 4);
    }
#pragma unroll
    for (int i = 0; i < 2; ++i) {                      // B: 1024 x 16B
        int idx = tid + i * NTHREADS;
        int n = idx >> 3, c = idx & 7;
        cp_async16(bAddr + (uint32_t)(n * (B_ROW_H * 2) + c * 16),
                   Bh + (size_t)(N0 + n) * ldb + k0 + c * 8);
    }
}

// MODE 0: g_Ph[n][i] = fp16( sum_k inputs[i][k] * W[k][n] )     (B = g_Wt, device-side)
// MODE 1: out[r][n]  = tanh((sum_k adj[r][k]*P[k][n] + P_self) / (rowsum(adj[r])+1) + b[n])
template <int MODE>
__global__ void __launch_bounds__(NTHREADS, 1)
gemm_gcn(const float* __restrict__ A,
         float* __restrict__ out, const float* __restrict__ bias) {
    extern __shared__ char smem[];
    float* sdeg = (float*)smem;

    // device-side global selection — NEVER pass __device__ symbols from host code
    const __half* __restrict__ Bh = (MODE == 0) ? g_Wt : g_Ph;

    const int tid = threadIdx.x;
    const int lane = tid & 31;
    const int wid = tid >> 5;
    const int wm = wid >> 2;            // 0..3 (32 rows each)
    const int wn = wid & 3;             // 0..3 (32 cols each)
    const int q = lane >> 2;            // 0..7
    const int c4 = lane & 3;            // 0..3

    const int Mt = blockIdx.x >> 1;
    const int Nt = blockIdx.x & 1;
    const int R0 = Mt * BM;
    const int N0 = Nt * BN;

    const int lda = (MODE == 0) ? HD : NR;
    const int ldb = (MODE == 0) ? HD : NR;
    const int NCH = ((MODE == 0) ? HD : NR) / BK;
    const bool doDeg = (MODE == 1) && (wn == 0);

    float acc[2][4][4];
#pragma unroll
    for (int i = 0; i < 2; ++i)
#pragma unroll
        for (int j = 0; j < 4; ++j)
#pragma unroll
            for (int e = 0; e < 4; ++e) acc[i][j][e] = 0.0f;
    float dsum[2][2];
    dsum[0][0] = dsum[0][1] = dsum[1][0] = dsum[1][1] = 0.0f;

    load_chunk(smem, 0, A, lda, R0, Bh, ldb, N0, 0, tid);
    cp_commit();
    load_chunk(smem, 1, A, lda, R0, Bh, ldb, N0, BK, tid);
    cp_commit();

    const int aBase = (wm * 32 + q) * A_ROW_F + 2 * c4;   // float index
    const int bBase = (wn * 32 + q) * B_ROW_H + 2 * c4;   // half index

    for (int kc = 0; kc < NCH; ++kc) {
        if (kc + 2 < NCH) cp_wait<1>(); else cp_wait<0>();
        __syncthreads();
        if (kc + 2 < NCH) {
            load_chunk(smem, (kc + 2) % STAGES, A, lda, R0, Bh, ldb, N0, (kc + 2) * BK, tid);
            cp_commit();
        }

        const float* aS = (const float*)(smem + SMEM_A_OFF + (kc % STAGES) * A_STAGE_B);
        const __half* bS = (const __half*)(smem + SMEM_B_OFF + (kc % STAGES) * B_STAGE_B);

#pragma unroll
        for (int ks = 0; ks < BK / 16; ++ks) {            // 4 k16 steps
            uint32_t af[2][4], bf[4][2];
#pragma unroll
            for (int mt = 0; mt < 2; ++mt) {
                int base = aBase + mt * 16 * A_ROW_F + ks * 16;
                float2 f0 = *(const float2*)&aS[base];                    // row q,   k,k+1
                float2 f1 = *(const float2*)&aS[base + 8 * A_ROW_F];      // row q+8, k,k+1
                float2 f2 = *(const float2*)&aS[base + 8];                // row q,   k+8,k+9
                float2 f3 = *(const float2*)&aS[base + 8 * A_ROW_F + 8];  // row q+8, k+8,k+9
                if (doDeg) {
                    dsum[mt][0] += (f0.x + f0.y) + (f2.x + f2.y);
                    dsum[mt][1] += (f1.x + f1.y) + (f3.x + f3.y);
                }
                af[mt][0] = pack_h2(f0.x, f0.y);
                af[mt][1] = pack_h2(f1.x, f1.y);
                af[mt][2] = pack_h2(f2.x, f2.y);
                af[mt][3] = pack_h2(f3.x, f3.y);
            }
#pragma unroll
            for (int nt = 0; nt < 4; ++nt) {
                int base = bBase + nt * 8 * B_ROW_H + ks * 16;
                bf[nt][0] = *(const uint32_t*)&bS[base];      // n-row, k,k+1
                bf[nt][1] = *(const uint32_t*)&bS[base + 8];  // n-row, k+8,k+9
            }
#pragma unroll
            for (int mt = 0; mt < 2; ++mt)
#pragma unroll
                for (int nt = 0; nt < 4; ++nt)
                    mma_f16(acc[mt][nt], af[mt], bf[nt]);
        }
    }
    __syncthreads();

    if (MODE == 0) {
        // write P transposed n-major fp16: g_Ph[n][row]
#pragma unroll
        for (int mt = 0; mt < 2; ++mt) {
            int rlo = R0 + wm * 32 + mt * 16 + q;
            int rhi = rlo + 8;
#pragma unroll
            for (int nt = 0; nt < 4; ++nt) {
                int col = N0 + wn * 32 + nt * 8 + 2 * c4;
                g_Ph[(size_t)col * NR + rlo]       = __float2half(acc[mt][nt][0]);
                g_Ph[(size_t)(col + 1) * NR + rlo] = __float2half(acc[mt][nt][1]);
                g_Ph[(size_t)col * NR + rhi]       = __float2half(acc[mt][nt][2]);
                g_Ph[(size_t)(col + 1) * NR + rhi] = __float2half(acc[mt][nt][3]);
            }
        }
    } else {
        if (doDeg) {
#pragma unroll
            for (int mt = 0; mt < 2; ++mt) {
#pragma unroll
                for (int h = 0; h < 2; ++h) {
                    float v = dsum[mt][h];
                    v += __shfl_xor_sync(0xffffffffu, v, 1);
                    v += __shfl_xor_sync(0xffffffffu, v, 2);
                    dsum[mt][h] = v;
                }
                if (c4 == 0) {
                    sdeg[wm * 32 + mt * 16 + q] = dsum[mt][0];
                    sdeg[wm * 32 + mt * 16 + q + 8] = dsum[mt][1];
                }
            }
        }
        __syncthreads();
#pragma unroll
        for (int mt = 0; mt < 2; ++mt) {
            int lrow = wm * 32 + mt * 16 + q;
            int rlo = R0 + lrow;
            int rhi = rlo + 8;
            float invlo = 1.0f / (sdeg[lrow] + 1.0f);
            float invhi = 1.0f / (sdeg[lrow + 8] + 1.0f);
#pragma unroll
            for (int nt = 0; nt < 4; ++nt) {
                int col = N0 + wn * 32 + nt * 8 + 2 * c4;
                float p00 = __half2float(g_Ph[(size_t)col * NR + rlo]);
                float p01 = __half2float(g_Ph[(size_t)(col + 1) * NR + rlo]);
                float p10 = __half2float(g_Ph[(size_t)col * NR + rhi]);
                float p11 = __half2float(g_Ph[(size_t)(col + 1) * NR + rhi]);
                float b0 = bias[col], b1 = bias[col + 1];
                float2 olo, ohi;
                olo.x = tanhf((acc[mt][nt][0] + p00) * invlo + b0);
                olo.y = tanhf((acc[mt][nt][1] + p01) * invlo + b1);
                ohi.x = tanhf((acc[mt][nt][2] + p10) * invhi + b0);
                ohi.y = tanhf((acc[mt][nt][3] + p11) * invhi + b1);
                *(float2*)&out[(size_t)rlo * HD + col] = olo;
                *(float2*)&out[(size_t)rhi * HD + col] = ohi;
            }
        }
    }
}

// W[k][n] fp32 -> g_Wt[n][k] fp16
__global__ void __launch_bounds__(1024, 1) prep_W(const float* __restrict__ W) {
    __shared__ float t[32][33];
    int x0 = blockIdx.x * 32, y0 = blockIdx.y * 32;
    t[threadIdx.y][threadIdx.x] = W[(size_t)(y0 + threadIdx.y) * HD + x0 + threadIdx.x];
    __syncthreads();
    g_Wt[(size_t)(x0 + threadIdx.y) * HD + y0 + threadIdx.x] = __float2half(t[threadIdx.x][threadIdx.y]);
}

extern "C" void kernel_launch(void* const* d_in, const int* in_sizes, int n_in,
                              void* d_out, int out_size) {
    const float* inputs = (const float*)d_in[0];
    const float* adj    = (const float*)d_in[1];
    const float* W      = (const float*)d_in[2];
    const float* b      = (const float*)d_in[3];
    float* out = (float*)d_out;

    cudaFuncSetAttribute(gemm_gcn<0>, cudaFuncAttributeMaxDynamicSharedMemorySize, SMEM_TOTAL);
    cudaFuncSetAttribute(gemm_gcn<1>, cudaFuncAttributeMaxDynamicSharedMemorySize, SMEM_TOTAL);

    prep_W<<<dim3(HD / 32, HD / 32), dim3(32, 32)>>>(W);
    gemm_gcn<0><<<(NR / BM) * (HD / BN), NTHREADS, SMEM_TOTAL>>>(inputs, nullptr, nullptr);
    gemm_gcn<1><<<(NR / BM) * (HD / BN), NTHREADS, SMEM_TOTAL>>>(adj, out, b);
}

// round 11
// speedup vs baseline: 1.4449x; 1.0013x over previous
#include <cuda_runtime.h>
#include <cuda_fp16.h>
#include <cstdint>
#include <cstddef>
#include <math.h>

#define DI __device__ __forceinline__

static constexpr int NR = 8192;
static constexpr int HD = 256;
static constexpr int BM = 128;
static constexpr int BN = 128;
static constexpr int BK = 64;
static constexpr int STAGES = 3;
static constexpr int NTHREADS = 512;    // 16 warps: 4(M) x 4(N), warp tile 32x32

static constexpr int A_ROW_F = 72;      // fp32 floats per A SMEM row (64 data + 8 pad)
static constexpr int B_ROW_H = 72;      // fp16 halves per B SMEM row (64 data + 8 pad)
static constexpr int A_STAGE_B = 128 * A_ROW_F * 4;   // 36864
static constexpr int B_STAGE_B = 128 * B_ROW_H * 2;   // 18432
static constexpr int SMEM_DEG_B = 512;
static constexpr int SMEM_A_OFF = SMEM_DEG_B;
static constexpr int SMEM_B_OFF = SMEM_A_OFF + STAGES * A_STAGE_B;
static constexpr int SMEM_TOTAL = SMEM_B_OFF + STAGES * B_STAGE_B;  // 166400

__device__ __half g_Wt[HD * HD];              // W transposed: [n][k] fp16
__device__ __half g_Ph[(size_t)HD * NR];      // P transposed: [n][k] fp16  (P = inputs @ W)

DI uint32_t smem_u32(const void* p) {
    uint32_t a;
    asm("{ .reg .u64 t; cvta.to.shared.u64 t, %1; cvt.u32.u64 %0, t; }" : "=r"(a) : "l"(p));
    return a;
}
DI void cp_async16(uint32_t dst, const void* src) {
    asm volatile("cp.async.cg.shared.global [%0], [%1], 16;" :: "r"(dst), "l"(src) : "memory");
}
DI void cp_commit() { asm volatile("cp.async.commit_group;" ::: "memory"); }
template <int N> DI void cp_wait() { asm volatile("cp.async.wait_group %0;" :: "n"(N) : "memory"); }
DI uint32_t pack_h2(float lo, float hi) {     // result .lo=lo, .hi=hi
    uint32_t d;
    asm("cvt.rn.f16x2.f32 %0, %1, %2;" : "=r"(d) : "f"(hi), "f"(lo));
    return d;
}
DI void mma_f16(float* d, const uint32_t* a, const uint32_t* b) {
    asm volatile(
        "mma.sync.aligned.m16n8k16.row.col.f32.f16.f16.f32 "
        "{%0,%1,%2,%3}, {%4,%5,%6,%7}, {%8,%9}, {%0,%1,%2,%3};"
        : "+f"(d[0]), "+f"(d[1]), "+f"(d[2]), "+f"(d[3])
        : "r"(a[0]), "r"(a[1]), "r"(a[2]), "r"(a[3]), "r"(b[0]), "r"(b[1]));
}

// fast tanh: 1 - 2/(e^{2x}+1). 2 MUFU (ex2, rcp) + few FMA; rel err ~2e-6; saturates correctly.
DI float fast_tanh(float x) {
    float e = __expf(2.0f * x);
    return 1.0f - __fdividef(2.0f, e + 1.0f);
}

// A tile [BM][BK] fp32 from row-major A; B tile [BN n-rows][BK k] fp16 from n-major Bh
DI void load_chunk(char* smem, int s,
                   const float* __restrict__ A, int lda, int R0,
                   const __half* __restrict__ Bh, int ldb, int N0,
                   int k0, int tid) {
    uint32_t aAddr = smem_u32(smem + SMEM_A_OFF + s * A_STAGE_B);
    uint32_t bAddr = smem_u32(smem + SMEM_B_OFF + s * B_STAGE_B);
#pragma unroll
    for (int i = 0; i < 4; ++i) {                      // A: 2048 x 16B
        int idx = tid + i * NTHREADS;
        int r = idx >> 4, c = idx & 15;
        cp_async16(aAddr + (uint32_t)(r * (A_ROW_F * 4) + c * 16),
                   A + (size_t)(R0 + r) * lda + k0 + c * 4);
    }
#pragma unroll
    for (int i = 0; i < 2; ++i) {                      // B: 1024 x 16B
        int idx = tid + i * NTHREADS;
        int n = idx >> 3, c = idx & 7;
        cp_async16(bAddr + (uint32_t)(n * (B_ROW_H * 2) + c * 16),
                   Bh + (size_t)(N0 + n) * ldb + k0 + c * 8);
    }
}

// MODE 0: g_Ph[n][i] = fp16( sum_k inputs[i][k] * W[k][n] )     (B = g_Wt, device-side)
// MODE 1: out[r][n]  = tanh((sum_k adj[r][k]*P[k][n] + P_self) / (rowsum(adj[r])+1) + b[n])
template <int MODE>
__global__ void __launch_bounds__(NTHREADS, 1)
gemm_gcn(const float* __restrict__ A,
         float* __restrict__ out, const float* __restrict__ bias) {
    extern __shared__ char smem[];
    float* sdeg = (float*)smem;

    // device-side global selection — NEVER pass __device__ symbols from host code
    const __half* __restrict__ Bh = (MODE == 0) ? g_Wt : g_Ph;

    const int tid = threadIdx.x;
    const int lane = tid & 31;
    const int wid = tid >> 5;
    const int wm = wid >> 2;            // 0..3 (32 rows each)
    const int wn = wid & 3;             // 0..3 (32 cols each)
    const int q = lane >> 2;            // 0..7
    const int c4 = lane & 3;            // 0..3

    const int Mt = blockIdx.x >> 1;
    const int Nt = blockIdx.x & 1;
    const int R0 = Mt * BM;
    const int N0 = Nt * BN;

    const int lda = (MODE == 0) ? HD : NR;
    const int ldb = (MODE == 0) ? HD : NR;
    const int NCH = ((MODE == 0) ? HD : NR) / BK;
    const bool doDeg = (MODE == 1) && (wn == 0);

    float acc[2][4][4];
#pragma unroll
    for (int i = 0; i < 2; ++i)
#pragma unroll
        for (int j = 0; j < 4; ++j)
#pragma unroll
            for (int e = 0; e < 4; ++e) acc[i][j][e] = 0.0f;
    float dsum[2][2];
    dsum[0][0] = dsum[0][1] = dsum[1][0] = dsum[1][1] = 0.0f;

    load_chunk(smem, 0, A, lda, R0, Bh, ldb, N0, 0, tid);
    cp_commit();
    load_chunk(smem, 1, A, lda, R0, Bh, ldb, N0, BK, tid);
    cp_commit();

    const int aBase = (wm * 32 + q) * A_ROW_F + 2 * c4;   // float index
    const int bBase = (wn * 32 + q) * B_ROW_H + 2 * c4;   // half index

    for (int kc = 0; kc < NCH; ++kc) {
        if (kc + 2 < NCH) cp_wait<1>(); else cp_wait<0>();
        __syncthreads();
        if (kc + 2 < NCH) {
            load_chunk(smem, (kc + 2) % STAGES, A, lda, R0, Bh, ldb, N0, (kc + 2) * BK, tid);
            cp_commit();
        }

        const float* aS = (const float*)(smem + SMEM_A_OFF + (kc % STAGES) * A_STAGE_B);
        const __half* bS = (const __half*)(smem + SMEM_B_OFF + (kc % STAGES) * B_STAGE_B);

#pragma unroll
        for (int ks = 0; ks < BK / 16; ++ks) {            // 4 k16 steps
            uint32_t af[2][4], bf[4][2];
#pragma unroll
            for (int mt = 0; mt < 2; ++mt) {
                int base = aBase + mt * 16 * A_ROW_F + ks * 16;
                float2 f0 = *(const float2*)&aS[base];                    // row q,   k,k+1
                float2 f1 = *(const float2*)&aS[base + 8 * A_ROW_F];      // row q+8, k,k+1
                float2 f2 = *(const float2*)&aS[base + 8];                // row q,   k+8,k+9
                float2 f3 = *(const float2*)&aS[base + 8 * A_ROW_F + 8];  // row q+8, k+8,k+9
                if (doDeg) {
                    dsum[mt][0] += (f0.x + f0.y) + (f2.x + f2.y);
                    dsum[mt][1] += (f1.x + f1.y) + (f3.x + f3.y);
                }
                af[mt][0] = pack_h2(f0.x, f0.y);
                af[mt][1] = pack_h2(f1.x, f1.y);
                af[mt][2] = pack_h2(f2.x, f2.y);
                af[mt][3] = pack_h2(f3.x, f3.y);
            }
#pragma unroll
            for (int nt = 0; nt < 4; ++nt) {
                int base = bBase + nt * 8 * B_ROW_H + ks * 16;
                bf[nt][0] = *(const uint32_t*)&bS[base];      // n-row, k,k+1
                bf[nt][1] = *(const uint32_t*)&bS[base + 8];  // n-row, k+8,k+9
            }
#pragma unroll
            for (int mt = 0; mt < 2; ++mt)
#pragma unroll
                for (int nt = 0; nt < 4; ++nt)
                    mma_f16(acc[mt][nt], af[mt], bf[nt]);
        }
    }
    __syncthreads();

    if (MODE == 0) {
        // write P transposed n-major fp16: g_Ph[n][row]
#pragma unroll
        for (int mt = 0; mt < 2; ++mt) {
            int rlo = R0 + wm * 32 + mt * 16 + q;
            int rhi = rlo + 8;
#pragma unroll
            for (int nt = 0; nt < 4; ++nt) {
                int col = N0 + wn * 32 + nt * 8 + 2 * c4;
                g_Ph[(size_t)col * NR + rlo]       = __float2half(acc[mt][nt][0]);
                g_Ph[(size_t)(col + 1) * NR + rlo] = __float2half(acc[mt][nt][1]);
                g_Ph[(size_t)col * NR + rhi]       = __float2half(acc[mt][nt][2]);
                g_Ph[(size_t)(col + 1) * NR + rhi] = __float2half(acc[mt][nt][3]);
            }
        }
    } else {
        if (doDeg) {
#pragma unroll
            for (int mt = 0; mt < 2; ++mt) {
#pragma unroll
                for (int h = 0; h < 2; ++h) {
                    float v = dsum[mt][h];
                    v += __shfl_xor_sync(0xffffffffu, v, 1);
                    v += __shfl_xor_sync(0xffffffffu, v, 2);
                    dsum[mt][h] = v;
                }
                if (c4 == 0) {
                    sdeg[wm * 32 + mt * 16 + q] = dsum[mt][0];
                    sdeg[wm * 32 + mt * 16 + q + 8] = dsum[mt][1];
                }
            }
        }
        __syncthreads();
#pragma unroll
        for (int mt = 0; mt < 2; ++mt) {
            int lrow = wm * 32 + mt * 16 + q;
            int rlo = R0 + lrow;
            int rhi = rlo + 8;
            float invlo = 1.0f / (sdeg[lrow] + 1.0f);
            float invhi = 1.0f / (sdeg[lrow + 8] + 1.0f);
#pragma unroll
            for (int nt = 0; nt < 4; ++nt) {
                int col = N0 + wn * 32 + nt * 8 + 2 * c4;
                float p00 = __half2float(g_Ph[(size_t)col * NR + rlo]);
                float p01 = __half2float(g_Ph[(size_t)(col + 1) * NR + rlo]);
                float p10 = __half2float(g_Ph[(size_t)col * NR + rhi]);
                float p11 = __half2float(g_Ph[(size_t)(col + 1) * NR + rhi]);
                float b0 = bias[col], b1 = bias[col + 1];
                float2 olo, ohi;
                olo.x = fast_tanh((acc[mt][nt][0] + p00) * invlo + b0);
                olo.y = fast_tanh((acc[mt][nt][1] + p01) * invlo + b1);
                ohi.x = fast_tanh((acc[mt][nt][2] + p10) * invhi + b0);
                ohi.y = fast_tanh((acc[mt][nt][3] + p11) * invhi + b1);
                *(float2*)&out[(size_t)rlo * HD + col] = olo;
                *(float2*)&out[(size_t)rhi * HD + col] = ohi;
            }
        }
    }
}

// W[k][n] fp32 -> g_Wt[n][k] fp16
__global__ void __launch_bounds__(1024, 1) prep_W(const float* __restrict__ W) {
    __shared__ float t[32][33];
    int x0 = blockIdx.x * 32, y0 = blockIdx.y * 32;
    t[threadIdx.y][threadIdx.x] = W[(size_t)(y0 + threadIdx.y) * HD + x0 + threadIdx.x];
    __syncthreads();
    g_Wt[(size_t)(x0 + threadIdx.y) * HD + y0 + threadIdx.x] = __float2half(t[threadIdx.x][threadIdx.y]);
}

extern "C" void kernel_launch(void* const* d_in, const int* in_sizes, int n_in,
                              void* d_out, int out_size) {
    const float* inputs = (const float*)d_in[0];
    const float* adj    = (const float*)d_in[1];
    const float* W      = (const float*)d_in[2];
    const float* b      = (const float*)d_in[3];
    float* out = (float*)d_out;

    cudaFuncSetAttribute(gemm_gcn<0>, cudaFuncAttributeMaxDynamicSharedMemorySize, SMEM_TOTAL);
    cudaFuncSetAttribute(gemm_gcn<1>, cudaFuncAttributeMaxDynamicSharedMemorySize, SMEM_TOTAL);

    prep_W<<<dim3(HD / 32, HD / 32), dim3(32, 32)>>>(W);
    gemm_gcn<0><<<(NR / BM) * (HD / BN), NTHREADS, SMEM_TOTAL>>>(inputs, nullptr, nullptr);
    gemm_gcn<1><<<(NR / BM) * (HD / BN), NTHREADS, SMEM_TOTAL>>>(adj, out, b);
}

// round 12
// speedup vs baseline: 1.4913x; 1.0321x over previous
#include <cuda_runtime.h>
#include <cuda_fp16.h>
#include <cstdint>
#include <cstddef>
#include <math.h>

#define DI __device__ __forceinline__

static constexpr int NR = 8192;
static constexpr int HD = 256;
static constexpr int BM = 64;
static constexpr int BN = 128;
static constexpr int BK = 64;
static constexpr int STAGES = 3;
static constexpr int NTHREADS = 256;    // 8 warps: 2(M) x 4(N), warp tile 32x32

static constexpr int A_ROW_F = 72;      // fp32 floats per A SMEM row (64 data + 8 pad)
static constexpr int B_ROW_H = 72;      // fp16 halves per B SMEM row (64 data + 8 pad)
static constexpr int A_STAGE_B = 64 * A_ROW_F * 4;    // 18432
static constexpr int B_STAGE_B = 128 * B_ROW_H * 2;   // 18432
static constexpr int SMEM_DEG_B = 512;
static constexpr int SMEM_A_OFF = SMEM_DEG_B;
static constexpr int SMEM_B_OFF = SMEM_A_OFF + STAGES * A_STAGE_B;
static constexpr int SMEM_TOTAL = SMEM_B_OFF + STAGES * B_STAGE_B;  // 111104 -> 2 CTAs/SM

__device__ __half g_Wt[HD * HD];              // W transposed: [n][k] fp16
__device__ __half g_Ph[(size_t)HD * NR];      // P transposed: [n][k] fp16  (P = inputs @ W)

DI uint32_t smem_u32(const void* p) {
    uint32_t a;
    asm("{ .reg .u64 t; cvta.to.shared.u64 t, %1; cvt.u32.u64 %0, t; }" : "=r"(a) : "l"(p));
    return a;
}
DI void cp_async16(uint32_t dst, const void* src) {
    asm volatile("cp.async.cg.shared.global [%0], [%1], 16;" :: "r"(dst), "l"(src) : "memory");
}
DI void cp_commit() { asm volatile("cp.async.commit_group;" ::: "memory"); }
template <int N> DI void cp_wait() { asm volatile("cp.async.wait_group %0;" :: "n"(N) : "memory"); }
DI uint32_t pack_h2(float lo, float hi) {     // result .lo=lo, .hi=hi
    uint32_t d;
    asm("cvt.rn.f16x2.f32 %0, %1, %2;" : "=r"(d) : "f"(hi), "f"(lo));
    return d;
}
DI void mma_f16(float* d, const uint32_t* a, const uint32_t* b) {
    asm volatile(
        "mma.sync.aligned.m16n8k16.row.col.f32.f16.f16.f32 "
        "{%0,%1,%2,%3}, {%4,%5,%6,%7}, {%8,%9}, {%0,%1,%2,%3};"
        : "+f"(d[0]), "+f"(d[1]), "+f"(d[2]), "+f"(d[3])
        : "r"(a[0]), "r"(a[1]), "r"(a[2]), "r"(a[3]), "r"(b[0]), "r"(b[1]));
}

// fast tanh: 1 - 2/(e^{2x}+1); rel err ~2e-6; saturates correctly.
DI float fast_tanh(float x) {
    float e = __expf(2.0f * x);
    return 1.0f - __fdividef(2.0f, e + 1.0f);
}

// A tile [BM][BK] fp32 from row-major A; B tile [BN n-rows][BK k] fp16 from n-major Bh
DI void load_chunk(char* smem, int s,
                   const float* __restrict__ A, int lda, int R0,
                   const __half* __restrict__ Bh, int ldb, int N0,
                   int k0, int tid) {
    uint32_t aAddr = smem_u32(smem + SMEM_A_OFF + s * A_STAGE_B);
    uint32_t bAddr = smem_u32(smem + SMEM_B_OFF + s * B_STAGE_B);
#pragma unroll
    for (int i = 0; i < 4; ++i) {                      // A: 1024 x 16B (64 rows x 16 granules)
        int idx = tid + i * NTHREADS;
        int r = idx >> 4, c = idx & 15;
        cp_async16(aAddr + (uint32_t)(r * (A_ROW_F * 4) + c * 16),
                   A + (size_t)(R0 + r) * lda + k0 + c * 4);
    }
#pragma unroll
    for (int i = 0; i < 4; ++i) {                      // B: 1024 x 16B (128 n-rows x 8 granules)
        int idx = tid + i * NTHREADS;
        int n = idx >> 3, c = idx & 7;
        cp_async16(bAddr + (uint32_t)(n * (B_ROW_H * 2) + c * 16),
                   Bh + (size_t)(N0 + n) * ldb + k0 + c * 8);
    }
}

// MODE 0: g_Ph[n][i] = fp16( sum_k inputs[i][k] * W[k][n] )     (B = g_Wt, device-side)
// MODE 1: out[r][n]  = tanh((sum_k adj[r][k]*P[k][n] + P_self) / (rowsum(adj[r])+1) + b[n])
template <int MODE>
__global__ void __launch_bounds__(NTHREADS, 2)
gemm_gcn(const float* __restrict__ A,
         float* __restrict__ out, const float* __restrict__ bias) {
    extern __shared__ char smem[];
    float* sdeg = (float*)smem;

    // device-side global selection — NEVER pass __device__ symbols from host code
    const __half* __restrict__ Bh = (MODE == 0) ? g_Wt : g_Ph;

    const int tid = threadIdx.x;
    const int lane = tid & 31;
    const int wid = tid >> 5;
    const int wm = wid >> 2;            // 0..1 (32 rows each)
    const int wn = wid & 3;             // 0..3 (32 cols each)
    const int q = lane >> 2;            // 0..7
    const int c4 = lane & 3;            // 0..3

    const int Mt = blockIdx.x >> 1;
    const int Nt = blockIdx.x & 1;
    const int R0 = Mt * BM;
    const int N0 = Nt * BN;

    const int lda = (MODE == 0) ? HD : NR;
    const int ldb = (MODE == 0) ? HD : NR;
    const int NCH = ((MODE == 0) ? HD : NR) / BK;
    const bool doDeg = (MODE == 1) && (wn == 0);

    float acc[2][4][4];
#pragma unroll
    for (int i = 0; i < 2; ++i)
#pragma unroll
        for (int j = 0; j < 4; ++j)
#pragma unroll
            for (int e = 0; e < 4; ++e) acc[i][j][e] = 0.0f;
    float dsum[2][2];
    dsum[0][0] = dsum[0][1] = dsum[1][0] = dsum[1][1] = 0.0f;

    load_chunk(smem, 0, A, lda, R0, Bh, ldb, N0, 0, tid);
    cp_commit();
    load_chunk(smem, 1, A, lda, R0, Bh, ldb, N0, BK, tid);
    cp_commit();

    const int aBase = (wm * 32 + q) * A_ROW_F + 2 * c4;   // float index
    const int bBase = (wn * 32 + q) * B_ROW_H + 2 * c4;   // half index

    for (int kc = 0; kc < NCH; ++kc) {
        if (kc + 2 < NCH) cp_wait<1>(); else cp_wait<0>();
        __syncthreads();
        if (kc + 2 < NCH) {
            load_chunk(smem, (kc + 2) % STAGES, A, lda, R0, Bh, ldb, N0, (kc + 2) * BK, tid);
            cp_commit();
        }

        const float* aS = (const float*)(smem + SMEM_A_OFF + (kc % STAGES) * A_STAGE_B);
        const __half* bS = (const __half*)(smem + SMEM_B_OFF + (kc % STAGES) * B_STAGE_B);

#pragma unroll
        for (int ks = 0; ks < BK / 16; ++ks) {            // 4 k16 steps
            uint32_t af[2][4], bf[4][2];
#pragma unroll
            for (int mt = 0; mt < 2; ++mt) {
                int base = aBase + mt * 16 * A_ROW_F + ks * 16;
                float2 f0 = *(const float2*)&aS[base];                    // row q,   k,k+1
                float2 f1 = *(const float2*)&aS[base + 8 * A_ROW_F];      // row q+8, k,k+1
                float2 f2 = *(const float2*)&aS[base + 8];                // row q,   k+8,k+9
                float2 f3 = *(const float2*)&aS[base + 8 * A_ROW_F + 8];  // row q+8, k+8,k+9
                if (doDeg) {
                    dsum[mt][0] += (f0.x + f0.y) + (f2.x + f2.y);
                    dsum[mt][1] += (f1.x + f1.y) + (f3.x + f3.y);
                }
                af[mt][0] = pack_h2(f0.x, f0.y);
                af[mt][1] = pack_h2(f1.x, f1.y);
                af[mt][2] = pack_h2(f2.x, f2.y);
                af[mt][3] = pack_h2(f3.x, f3.y);
            }
#pragma unroll
            for (int nt = 0; nt < 4; ++nt) {
                int base = bBase + nt * 8 * B_ROW_H + ks * 16;
                bf[nt][0] = *(const uint32_t*)&bS[base];      // n-row, k,k+1
                bf[nt][1] = *(const uint32_t*)&bS[base + 8];  // n-row, k+8,k+9
            }
#pragma unroll
            for (int mt = 0; mt < 2; ++mt)
#pragma unroll
                for (int nt = 0; nt < 4; ++nt)
                    mma_f16(acc[mt][nt], af[mt], bf[nt]);
        }
    }
    __syncthreads();

    if (MODE == 0) {
        // write P transposed n-major fp16: g_Ph[n][row]
#pragma unroll
        for (int mt = 0; mt < 2; ++mt) {
            int rlo = R0 + wm * 32 + mt * 16 + q;
            int rhi = rlo + 8;
#pragma unroll
            for (int nt = 0; nt < 4; ++nt) {
                int col = N0 + wn * 32 + nt * 8 + 2 * c4;
                g_Ph[(size_t)col * NR + rlo]       = __float2half(acc[mt][nt][0]);
                g_Ph[(size_t)(col + 1) * NR + rlo] = __float2half(acc[mt][nt][1]);
                g_Ph[(size_t)col * NR + rhi]       = __float2half(acc[mt][nt][2]);
                g_Ph[(size_t)(col + 1) * NR + rhi] = __float2half(acc[mt][nt][3]);
            }
        }
    } else {
        if (doDeg) {
#pragma unroll
            for (int mt = 0; mt < 2; ++mt) {
#pragma unroll
                for (int h = 0; h < 2; ++h) {
                    float v = dsum[mt][h];
                    v += __shfl_xor_sync(0xffffffffu, v, 1);
                    v += __shfl_xor_sync(0xffffffffu, v, 2);
                    dsum[mt][h] = v;
                }
                if (c4 == 0) {
                    sdeg[wm * 32 + mt * 16 + q] = dsum[mt][0];
                    sdeg[wm * 32 + mt * 16 + q + 8] = dsum[mt][1];
                }
            }
        }
        __syncthreads();
#pragma unroll
        for (int mt = 0; mt < 2; ++mt) {
            int lrow = wm * 32 + mt * 16 + q;
            int rlo = R0 + lrow;
            int rhi = rlo + 8;
            float invlo = 1.0f / (sdeg[lrow] + 1.0f);
            float invhi = 1.0f / (sdeg[lrow + 8] + 1.0f);
#pragma unroll
            for (int nt = 0; nt < 4; ++nt) {
                int col = N0 + wn * 32 + nt * 8 + 2 * c4;
                float p00 = __half2float(g_Ph[(size_t)col * NR + rlo]);
                float p01 = __half2float(g_Ph[(size_t)(col + 1) * NR + rlo]);
                float p10 = __half2float(g_Ph[(size_t)col * NR + rhi]);
                float p11 = __half2float(g_Ph[(size_t)(col + 1) * NR + rhi]);
                float b0 = bias[col], b1 = bias[col + 1];
                float2 olo, ohi;
                olo.x = fast_tanh((acc[mt][nt][0] + p00) * invlo + b0);
                olo.y = fast_tanh((acc[mt][nt][1] + p01) * invlo + b1);
                ohi.x = fast_tanh((acc[mt][nt][2] + p10) * invhi + b0);
                ohi.y = fast_tanh((acc[mt][nt][3] + p11) * invhi + b1);
                *(float2*)&out[(size_t)rlo * HD + col] = olo;
                *(float2*)&out[(size_t)rhi * HD + col] = ohi;
            }
        }
    }
}

// W[k][n] fp32 -> g_Wt[n][k] fp16
__global__ void __launch_bounds__(1024, 1) prep_W(const float* __restrict__ W) {
    __shared__ float t[32][33];
    int x0 = blockIdx.x * 32, y0 = blockIdx.y * 32;
    t[threadIdx.y][threadIdx.x] = W[(size_t)(y0 + threadIdx.y) * HD + x0 + threadIdx.x];
    __syncthreads();
    g_Wt[(size_t)(x0 + threadIdx.y) * HD + y0 + threadIdx.x] = __float2half(t[threadIdx.x][threadIdx.y]);
}

extern "C" void kernel_launch(void* const* d_in, const int* in_sizes, int n_in,
                              void* d_out, int out_size) {
    const float* inputs = (const float*)d_in[0];
    const float* adj    = (const float*)d_in[1];
    const float* W      = (const float*)d_in[2];
    const float* b      = (const float*)d_in[3];
    float* out = (float*)d_out;

    cudaFuncSetAttribute(gemm_gcn<0>, cudaFuncAttributeMaxDynamicSharedMemorySize, SMEM_TOTAL);
    cudaFuncSetAttribute(gemm_gcn<1>, cudaFuncAttributeMaxDynamicSharedMemorySize, SMEM_TOTAL);

    prep_W<<<dim3(HD / 32, HD / 32), dim3(32, 32)>>>(W);
    gemm_gcn<0><<<(NR / BM) * (HD / BN), NTHREADS, SMEM_TOTAL>>>(inputs, nullptr, nullptr);
    gemm_gcn<1><<<(NR / BM) * (HD / BN), NTHREADS, SMEM_TOTAL>>>(adj, out, b);
}

// round 13
// speedup vs baseline: 1.5209x; 1.0199x over previous
#include <cuda_runtime.h>
#include <cuda_fp16.h>
#include <cstdint>
#include <cstddef>
#include <math.h>

#define DI __device__ __forceinline__

static constexpr int NR = 8192;
static constexpr int HD = 256;
static constexpr int BM = 64;
static constexpr int BN = 128;
static constexpr int BK = 64;
static constexpr int NTHREADS = 256;    // 8 warps: 2(M) x 4(N), warp tile 32x32

static constexpr int A_ROW_F = 72;      // fp32 floats per A SMEM row (64 data + 8 pad)
static constexpr int B_ROW_H = 72;      // fp16 halves per B SMEM row (64 data + 8 pad)
static constexpr int A_STAGE_B = 64 * A_ROW_F * 4;    // 18432
static constexpr int B_STAGE_B = 128 * B_ROW_H * 2;   // 18432
static constexpr int SMEM_DEG_B = 512;
static constexpr int SMEM_A_OFF = SMEM_DEG_B;
static constexpr int SMEM_B_OFF = SMEM_A_OFF + 2 * A_STAGE_B;
static constexpr int SMEM_TOTAL = SMEM_B_OFF + 2 * B_STAGE_B;  // 74240 -> 3 CTAs/SM

__device__ __half g_Wt[HD * HD];              // W transposed: [n][k] fp16
__device__ __half g_Ph[(size_t)HD * NR];      // P transposed: [n][k] fp16  (P = inputs @ W)

DI uint32_t smem_u32(const void* p) {
    uint32_t a;
    asm("{ .reg .u64 t; cvta.to.shared.u64 t, %1; cvt.u32.u64 %0, t; }" : "=r"(a) : "l"(p));
    return a;
}
DI void cp_async16(uint32_t dst, const void* src) {
    asm volatile("cp.async.cg.shared.global [%0], [%1], 16;" :: "r"(dst), "l"(src) : "memory");
}
DI void cp_commit() { asm volatile("cp.async.commit_group;" ::: "memory"); }
template <int N> DI void cp_wait() { asm volatile("cp.async.wait_group %0;" :: "n"(N) : "memory"); }
DI uint32_t pack_h2(float lo, float hi) {     // result .lo=lo, .hi=hi
    uint32_t d;
    asm("cvt.rn.f16x2.f32 %0, %1, %2;" : "=r"(d) : "f"(hi), "f"(lo));
    return d;
}
DI void mma_f16(float* d, const uint32_t* a, const uint32_t* b) {
    asm volatile(
        "mma.sync.aligned.m16n8k16.row.col.f32.f16.f16.f32 "
        "{%0,%1,%2,%3}, {%4,%5,%6,%7}, {%8,%9}, {%0,%1,%2,%3};"
        : "+f"(d[0]), "+f"(d[1]), "+f"(d[2]), "+f"(d[3])
        : "r"(a[0]), "r"(a[1]), "r"(a[2]), "r"(a[3]), "r"(b[0]), "r"(b[1]));
}

// fast tanh: 1 - 2/(e^{2x}+1); rel err ~2e-6; saturates correctly.
DI float fast_tanh(float x) {
    float e = __expf(2.0f * x);
    return 1.0f - __fdividef(2.0f, e + 1.0f);
}

// A tile [BM][BK] fp32 from row-major A; B tile [BN n-rows][BK k] fp16 from n-major Bh
DI void load_chunk(char* smem, int s,
                   const float* __restrict__ A, int lda, int R0,
                   const __half* __restrict__ Bh, int ldb, int N0,
                   int k0, int tid) {
    uint32_t aAddr = smem_u32(smem + SMEM_A_OFF + s * A_STAGE_B);
    uint32_t bAddr = smem_u32(smem + SMEM_B_OFF + s * B_STAGE_B);
#pragma unroll
    for (int i = 0; i < 4; ++i) {                      // A: 1024 x 16B (64 rows x 16 granules)
        int idx = tid + i * NTHREADS;
        int r = idx >> 4, c = idx & 15;
        cp_async16(aAddr + (uint32_t)(r * (A_ROW_F * 4) + c * 16),
                   A + (size_t)(R0 + r) * lda + k0 + c * 4);
    }
#pragma unroll
    for (int i = 0; i < 4; ++i) {                      // B: 1024 x 16B (128 n-rows x 8 granules)
        int idx = tid + i * NTHREADS;
        int n = idx >> 3, c = idx & 7;
        cp_async16(bAddr + (uint32_t)(n * (B_ROW_H * 2) + c * 16),
                   Bh + (size_t)(N0 + n) * ldb + k0 + c * 8);
    }
}

// MODE 0: g_Ph[n][i] = fp16( sum_k inputs[i][k] * W[k][n] )     (B = g_Wt, device-side)
// MODE 1: out[r][n]  = tanh((sum_k adj[r][k]*P[k][n] + P_self) / (rowsum(adj[r])+1) + b[n])
template <int MODE>
__global__ void __launch_bounds__(NTHREADS, 3)
gemm_gcn(const float* __restrict__ A,
         float* __restrict__ out, const float* __restrict__ bias) {
    extern __shared__ char smem[];
    float* sdeg = (float*)smem;

    // device-side global selection — NEVER pass __device__ symbols from host code
    const __half* __restrict__ Bh = (MODE == 0) ? g_Wt : g_Ph;

    const int tid = threadIdx.x;
    const int lane = tid & 31;
    const int wid = tid >> 5;
    const int wm = wid >> 2;            // 0..1 (32 rows each)
    const int wn = wid & 3;             // 0..3 (32 cols each)
    const int q = lane >> 2;            // 0..7
    const int c4 = lane & 3;            // 0..3

    const int Mt = blockIdx.x >> 1;
    const int Nt = blockIdx.x & 1;
    const int R0 = Mt * BM;
    const int N0 = Nt * BN;

    const int lda = (MODE == 0) ? HD : NR;
    const int ldb = (MODE == 0) ? HD : NR;
    const int NCH = ((MODE == 0) ? HD : NR) / BK;
    const bool doDeg = (MODE == 1) && (wn == 0);

    float acc[2][4][4];
#pragma unroll
    for (int i = 0; i < 2; ++i)
#pragma unroll
        for (int j = 0; j < 4; ++j)
#pragma unroll
            for (int e = 0; e < 4; ++e) acc[i][j][e] = 0.0f;
    float dsum[2][2];
    dsum[0][0] = dsum[0][1] = dsum[1][0] = dsum[1][1] = 0.0f;

    // 2-stage pipeline, prefetch distance 1
    load_chunk(smem, 0, A, lda, R0, Bh, ldb, N0, 0, tid);
    cp_commit();

    const int aBase = (wm * 32 + q) * A_ROW_F + 2 * c4;   // float index
    const int bBase = (wn * 32 + q) * B_ROW_H + 2 * c4;   // half index

    for (int kc = 0; kc < NCH; ++kc) {
        cp_wait<0>();                 // chunk kc resident
        __syncthreads();              // + all warps done reading stage kc%2 from chunk kc-2
        if (kc + 1 < NCH) {
            load_chunk(smem, (kc + 1) & 1, A, lda, R0, Bh, ldb, N0, (kc + 1) * BK, tid);
            cp_commit();
        }

        const float* aS = (const float*)(smem + SMEM_A_OFF + (kc & 1) * A_STAGE_B);
        const __half* bS = (const __half*)(smem + SMEM_B_OFF + (kc & 1) * B_STAGE_B);

#pragma unroll
        for (int ks = 0; ks < BK / 16; ++ks) {            // 4 k16 steps
            uint32_t af[2][4], bf[4][2];
#pragma unroll
            for (int mt = 0; mt < 2; ++mt) {
                int base = aBase + mt * 16 * A_ROW_F + ks * 16;
                float2 f0 = *(const float2*)&aS[base];                    // row q,   k,k+1
                float2 f1 = *(const float2*)&aS[base + 8 * A_ROW_F];      // row q+8, k,k+1
                float2 f2 = *(const float2*)&aS[base + 8];                // row q,   k+8,k+9
                float2 f3 = *(const float2*)&aS[base + 8 * A_ROW_F + 8];  // row q+8, k+8,k+9
                if (doDeg) {
                    dsum[mt][0] += (f0.x + f0.y) + (f2.x + f2.y);
                    dsum[mt][1] += (f1.x + f1.y) + (f3.x + f3.y);
                }
                af[mt][0] = pack_h2(f0.x, f0.y);
                af[mt][1] = pack_h2(f1.x, f1.y);
                af[mt][2] = pack_h2(f2.x, f2.y);
                af[mt][3] = pack_h2(f3.x, f3.y);
            }
#pragma unroll
            for (int nt = 0; nt < 4; ++nt) {
                int base = bBase + nt * 8 * B_ROW_H + ks * 16;
                bf[nt][0] = *(const uint32_t*)&bS[base];      // n-row, k,k+1
                bf[nt][1] = *(const uint32_t*)&bS[base + 8];  // n-row, k+8,k+9
            }
#pragma unroll
            for (int mt = 0; mt < 2; ++mt)
#pragma unroll
                for (int nt = 0; nt < 4; ++nt)
                    mma_f16(acc[mt][nt], af[mt], bf[nt]);
        }
    }
    __syncthreads();

    if (MODE == 0) {
        // write P transposed n-major fp16: g_Ph[n][row]
#pragma unroll
        for (int mt = 0; mt < 2; ++mt) {
            int rlo = R0 + wm * 32 + mt * 16 + q;
            int rhi = rlo + 8;
#pragma unroll
            for (int nt = 0; nt < 4; ++nt) {
                int col = N0 + wn * 32 + nt * 8 + 2 * c4;
                g_Ph[(size_t)col * NR + rlo]       = __float2half(acc[mt][nt][0]);
                g_Ph[(size_t)(col + 1) * NR + rlo] = __float2half(acc[mt][nt][1]);
                g_Ph[(size_t)col * NR + rhi]       = __float2half(acc[mt][nt][2]);
                g_Ph[(size_t)(col + 1) * NR + rhi] = __float2half(acc[mt][nt][3]);
            }
        }
    } else {
        if (doDeg) {
#pragma unroll
            for (int mt = 0; mt < 2; ++mt) {
#pragma unroll
                for (int h = 0; h < 2; ++h) {
                    float v = dsum[mt][h];
                    v += __shfl_xor_sync(0xffffffffu, v, 1);
                    v += __shfl_xor_sync(0xffffffffu, v, 2);
                    dsum[mt][h] = v;
                }
                if (c4 == 0) {
                    sdeg[wm * 32 + mt * 16 + q] = dsum[mt][0];
                    sdeg[wm * 32 + mt * 16 + q + 8] = dsum[mt][1];
                }
            }
        }
        __syncthreads();
#pragma unroll
        for (int mt = 0; mt < 2; ++mt) {
            int lrow = wm * 32 + mt * 16 + q;
            int rlo = R0 + lrow;
            int rhi = rlo + 8;
            float invlo = 1.0f / (sdeg[lrow] + 1.0f);
            float invhi = 1.0f / (sdeg[lrow + 8] + 1.0f);
#pragma unroll
            for (int nt = 0; nt < 4; ++nt) {
                int col = N0 + wn * 32 + nt * 8 + 2 * c4;
                float p00 = __half2float(g_Ph[(size_t)col * NR + rlo]);
                float p01 = __half2float(g_Ph[(size_t)(col + 1) * NR + rlo]);
                float p10 = __half2float(g_Ph[(size_t)col * NR + rhi]);
                float p11 = __half2float(g_Ph[(size_t)(col + 1) * NR + rhi]);
                float b0 = bias[col], b1 = bias[col + 1];
                float2 olo, ohi;
                olo.x = fast_tanh((acc[mt][nt][0] + p00) * invlo + b0);
                olo.y = fast_tanh((acc[mt][nt][1] + p01) * invlo + b1);
                ohi.x = fast_tanh((acc[mt][nt][2] + p10) * invhi + b0);
                ohi.y = fast_tanh((acc[mt][nt][3] + p11) * invhi + b1);
                *(float2*)&out[(size_t)rlo * HD + col] = olo;
                *(float2*)&out[(size_t)rhi * HD + col] = ohi;
            }
        }
    }
}

// W[k][n] fp32 -> g_Wt[n][k] fp16
__global__ void __launch_bounds__(1024, 1) prep_W(const float* __restrict__ W) {
    __shared__ float t[32][33];
    int x0 = blockIdx.x * 32, y0 = blockIdx.y * 32;
    t[threadIdx.y][threadIdx.x] = W[(size_t)(y0 + threadIdx.y) * HD + x0 + threadIdx.x];
    __syncthreads();
    g_Wt[(size_t)(x0 + threadIdx.y) * HD + y0 + threadIdx.x] = __float2half(t[threadIdx.x][threadIdx.y]);
}

extern "C" void kernel_launch(void* const* d_in, const int* in_sizes, int n_in,
                              void* d_out, int out_size) {
    const float* inputs = (const float*)d_in[0];
    const float* adj    = (const float*)d_in[1];
    const float* W      = (const float*)d_in[2];
    const float* b      = (const float*)d_in[3];
    float* out = (float*)d_out;

    cudaFuncSetAttribute(gemm_gcn<0>, cudaFuncAttributeMaxDynamicSharedMemorySize, SMEM_TOTAL);
    cudaFuncSetAttribute(gemm_gcn<1>, cudaFuncAttributeMaxDynamicSharedMemorySize, SMEM_TOTAL);

    prep_W<<<dim3(HD / 32, HD / 32), dim3(32, 32)>>>(W);
    gemm_gcn<0><<<(NR / BM) * (HD / BN), NTHREADS, SMEM_TOTAL>>>(inputs, nullptr, nullptr);
    gemm_gcn<1><<<(NR / BM) * (HD / BN), NTHREADS, SMEM_TOTAL>>>(adj, out, b);
}